// round 2
// baseline (speedup 1.0000x reference)
#include <cuda_runtime.h>

// Problem constants (fixed by the dataset).
#define D_IN   2048
#define D_OUT  2048
#define M_TOK  8192      // B*S = 4*2048
#define RANK   16
#define NEXP   8
#define SCALING 1.0f     // lora_alpha / r = 16/16

// Scratch for the folded weight matrix: W_eff = W + scaling * Bstack @ Astack.
// __device__ global => no runtime allocation (harness allocation guards).
__device__ float g_Weff[(size_t)D_OUT * D_IN];

// ---------------------------------------------------------------------------
// Kernel 1: fold LoRA into W.
//   W_eff[o,d] = W[o,d] + SCALING * sum_{k=0..127} Bs[o,k] * A[k,d]
// where k = 16*e + r, Bs[o,k] = mask[e] * lora_B[e,o,r],
// and A viewed as [128, D_IN] is exactly lora_A (contiguous).
// ---------------------------------------------------------------------------
__global__ __launch_bounds__(256) void fold_kernel(
    const float* __restrict__ W,
    const float* __restrict__ A,          // [128, D_IN]
    const float* __restrict__ Bl,         // [E, D_OUT, R]
    const int* __restrict__ mask)         // int32 (bool stored as i32)
{
    __shared__ __align__(16) float sB[16][132];   // [r][o_local]
    __shared__ __align__(16) float sA[16][132];   // [k_local][d_local]

    const int t  = threadIdx.x;
    const int tr = t >> 4;          // 0..15  (o micro-row)
    const int tc = t & 15;          // 0..15  (d micro-col)
    const int o0 = blockIdx.y * 128;
    const int d0 = blockIdx.x * 128;

    float acc[8][8];
#pragma unroll
    for (int i = 0; i < 8; ++i)
#pragma unroll
        for (int j = 0; j < 8; ++j) acc[i][j] = 0.f;

    for (int c = 0; c < NEXP; ++c) {
        const float sc = (mask[c] != 0) ? SCALING : 0.f;
        // Load Bs chunk: lora_B[c] is [D_OUT, R] row-major, r contiguous.
#pragma unroll
        for (int i = 0; i < 8; ++i) {
            int idx = t + i * 256;
            int ol = idx >> 4;      // 0..127
            int r  = idx & 15;      // 0..15
            sB[r][ol] = Bl[(size_t)c * D_OUT * RANK + (size_t)(o0 + ol) * RANK + r] * sc;
        }
        // Load A chunk: rows k = 16c..16c+15 over d tile.
#pragma unroll
        for (int i = 0; i < 8; ++i) {
            int idx = t + i * 256;
            int kk = idx >> 7;      // 0..15
            int dl = idx & 127;     // 0..127
            sA[kk][dl] = A[(size_t)(c * 16 + kk) * D_IN + d0 + dl];
        }
        __syncthreads();

#pragma unroll
        for (int kk = 0; kk < 16; ++kk) {
            float4 b0 = *(const float4*)&sB[kk][tr * 8];
            float4 b1 = *(const float4*)&sB[kk][tr * 8 + 4];
            float4 a0 = *(const float4*)&sA[kk][tc * 8];
            float4 a1 = *(const float4*)&sA[kk][tc * 8 + 4];
            float ov[8] = {b0.x, b0.y, b0.z, b0.w, b1.x, b1.y, b1.z, b1.w};
            float dv[8] = {a0.x, a0.y, a0.z, a0.w, a1.x, a1.y, a1.z, a1.w};
#pragma unroll
            for (int i = 0; i < 8; ++i)
#pragma unroll
                for (int j = 0; j < 8; ++j) acc[i][j] += ov[i] * dv[j];
        }
        __syncthreads();
    }

#pragma unroll
    for (int i = 0; i < 8; ++i) {
        int o = o0 + tr * 8 + i;
#pragma unroll
        for (int j = 0; j < 8; j += 4) {
            int d = d0 + tc * 8 + j;
            float4 w = *(const float4*)&W[(size_t)o * D_IN + d];
            float4 r;
            r.x = w.x + acc[i][j + 0];
            r.y = w.y + acc[i][j + 1];
            r.z = w.z + acc[i][j + 2];
            r.w = w.w + acc[i][j + 3];
            *(float4*)&g_Weff[(size_t)o * D_IN + d] = r;
        }
    }
}

// ---------------------------------------------------------------------------
// Kernel 2: main GEMM  out[m,n] = sum_k x[m,k] * W_eff[n,k] + bias[n]
// Both operands K-contiguous (NT). 128x128x16 tiles, 256 threads, 8x8 micro,
// double-buffered smem + register prefetch, one __syncthreads per K-step.
// ---------------------------------------------------------------------------
__global__ __launch_bounds__(256, 2) void gemm_kernel(
    const float* __restrict__ x,
    const float* __restrict__ bias,
    float* __restrict__ out)
{
    __shared__ __align__(16) float sX[2][16][132];   // [buf][k][m_local]
    __shared__ __align__(16) float sW[2][16][132];   // [buf][k][n_local]

    const int t  = threadIdx.x;
    const int tr = t >> 4;
    const int tc = t & 15;
    const int m0 = blockIdx.y * 128;
    const int n0 = blockIdx.x * 128;

    // float4 load coords: 512 float4 per tile, 2 per thread.
    const int ml0  = t >> 2;            // 0..63  (+64 for i=1)
    const int kl4  = t & 3;             // which float4 in k (0..3)

    float acc[8][8];
#pragma unroll
    for (int i = 0; i < 8; ++i)
#pragma unroll
        for (int j = 0; j < 8; ++j) acc[i][j] = 0.f;

    const int NKT = D_IN / 16;          // 128 k-tiles

    // Prime buffer 0.
#pragma unroll
    for (int i = 0; i < 2; ++i) {
        int ml = ml0 + i * 64;
        float4 vx = *(const float4*)&x[(size_t)(m0 + ml) * D_IN + kl4 * 4];
        float4 vw = *(const float4*)&g_Weff[(size_t)(n0 + ml) * D_IN + kl4 * 4];
        sX[0][kl4 * 4 + 0][ml] = vx.x; sX[0][kl4 * 4 + 1][ml] = vx.y;
        sX[0][kl4 * 4 + 2][ml] = vx.z; sX[0][kl4 * 4 + 3][ml] = vx.w;
        sW[0][kl4 * 4 + 0][ml] = vw.x; sW[0][kl4 * 4 + 1][ml] = vw.y;
        sW[0][kl4 * 4 + 2][ml] = vw.z; sW[0][kl4 * 4 + 3][ml] = vw.w;
    }
    __syncthreads();

    float4 rx4[2], rw4[2];

    for (int kt = 0; kt < NKT; ++kt) {
        const int buf = kt & 1;
        if (kt + 1 < NKT) {
            const int koff = (kt + 1) * 16 + kl4 * 4;
#pragma unroll
            for (int i = 0; i < 2; ++i) {
                int ml = ml0 + i * 64;
                rx4[i] = *(const float4*)&x[(size_t)(m0 + ml) * D_IN + koff];
                rw4[i] = *(const float4*)&g_Weff[(size_t)(n0 + ml) * D_IN + koff];
            }
        }

#pragma unroll
        for (int kk = 0; kk < 16; ++kk) {
            float4 a0 = *(const float4*)&sX[buf][kk][tr * 8];
            float4 a1 = *(const float4*)&sX[buf][kk][tr * 8 + 4];
            float4 w0 = *(const float4*)&sW[buf][kk][tc * 8];
            float4 w1 = *(const float4*)&sW[buf][kk][tc * 8 + 4];
            float av[8] = {a0.x, a0.y, a0.z, a0.w, a1.x, a1.y, a1.z, a1.w};
            float wv[8] = {w0.x, w0.y, w0.z, w0.w, w1.x, w1.y, w1.z, w1.w};
#pragma unroll
            for (int i = 0; i < 8; ++i)
#pragma unroll
                for (int j = 0; j < 8; ++j) acc[i][j] += av[i] * wv[j];
        }

        if (kt + 1 < NKT) {
            const int nb = buf ^ 1;
#pragma unroll
            for (int i = 0; i < 2; ++i) {
                int ml = ml0 + i * 64;
                sX[nb][kl4 * 4 + 0][ml] = rx4[i].x; sX[nb][kl4 * 4 + 1][ml] = rx4[i].y;
                sX[nb][kl4 * 4 + 2][ml] = rx4[i].z; sX[nb][kl4 * 4 + 3][ml] = rx4[i].w;
                sW[nb][kl4 * 4 + 0][ml] = rw4[i].x; sW[nb][kl4 * 4 + 1][ml] = rw4[i].y;
                sW[nb][kl4 * 4 + 2][ml] = rw4[i].z; sW[nb][kl4 * 4 + 3][ml] = rw4[i].w;
            }
            __syncthreads();
        }
    }

    // Epilogue: add bias, store float4.
    float bv[8];
#pragma unroll
    for (int j = 0; j < 8; j += 4) {
        float4 bb = *(const float4*)&bias[n0 + tc * 8 + j];
        bv[j] = bb.x; bv[j + 1] = bb.y; bv[j + 2] = bb.z; bv[j + 3] = bb.w;
    }
#pragma unroll
    for (int i = 0; i < 8; ++i) {
        int row = m0 + tr * 8 + i;
#pragma unroll
        for (int j = 0; j < 8; j += 4) {
            float4 r;
            r.x = acc[i][j + 0] + bv[j + 0];
            r.y = acc[i][j + 1] + bv[j + 1];
            r.z = acc[i][j + 2] + bv[j + 2];
            r.w = acc[i][j + 3] + bv[j + 3];
            *(float4*)&out[(size_t)row * D_OUT + n0 + tc * 8 + j] = r;
        }
    }
}

// ---------------------------------------------------------------------------
// Inputs (metadata order): x, W, b, lora_A, lora_B, expert_mask
// ---------------------------------------------------------------------------
extern "C" void kernel_launch(void* const* d_in, const int* in_sizes, int n_in,
                              void* d_out, int out_size)
{
    const float* x    = (const float*)d_in[0];
    const float* W    = (const float*)d_in[1];
    const float* b    = (const float*)d_in[2];
    const float* lA   = (const float*)d_in[3];
    const float* lB   = (const float*)d_in[4];
    const int*   mask = (const int*)d_in[5];
    float* out = (float*)d_out;

    dim3 blk(256);
    dim3 grid_fold(D_IN / 128, D_OUT / 128);     // (16,16)
    dim3 grid_gemm(D_OUT / 128, M_TOK / 128);    // (16,64)

    fold_kernel<<<grid_fold, blk>>>(W, lA, lB, mask);
    gemm_kernel<<<grid_gemm, blk>>>(x, b, out);
}

// round 4
// speedup vs baseline: 2.8284x; 2.8284x over previous
#include <cuda_runtime.h>
#include <cuda_bf16.h>
#include <cstdint>

#define D_IN   2048
#define D_OUT  2048
#define M_TOK  8192
#define RANK   16
#define NEXP   8
#define SCALING 1.0f

// Split bf16 operands (hi/lo), precomputed. ~80MB total, static device globals.
__device__ __nv_bfloat16 g_Xh[(size_t)M_TOK * D_IN];
__device__ __nv_bfloat16 g_Xl[(size_t)M_TOK * D_IN];
__device__ __nv_bfloat16 g_Wh[(size_t)D_OUT * D_IN];
__device__ __nv_bfloat16 g_Wl[(size_t)D_OUT * D_IN];

// ---------------------------------------------------------------------------
// helpers
// ---------------------------------------------------------------------------
__device__ __forceinline__ uint32_t smem_u32(const void* p) {
    uint32_t a;
    asm("{ .reg .u64 t; cvta.to.shared.u64 t, %1; cvt.u32.u64 %0, t; }" : "=r"(a) : "l"(p));
    return a;
}
__device__ __forceinline__ void cpa16(uint32_t s, const void* g) {
    asm volatile("cp.async.cg.shared.global [%0], [%1], 16;" :: "r"(s), "l"(g));
}
__device__ __forceinline__ void cpa_commit() {
    asm volatile("cp.async.commit_group;" ::: "memory");
}
template <int N> __device__ __forceinline__ void cpa_wait() {
    asm volatile("cp.async.wait_group %0;" :: "n"(N) : "memory");
}
__device__ __forceinline__ void ldsm_x4(uint32_t addr, uint32_t& r0, uint32_t& r1,
                                        uint32_t& r2, uint32_t& r3) {
    asm volatile("ldmatrix.sync.aligned.m8n8.x4.shared.b16 {%0,%1,%2,%3}, [%4];"
                 : "=r"(r0), "=r"(r1), "=r"(r2), "=r"(r3) : "r"(addr));
}
__device__ __forceinline__ void mma_bf16(float& c0, float& c1, float& c2, float& c3,
                                         uint32_t a0, uint32_t a1, uint32_t a2, uint32_t a3,
                                         uint32_t b0, uint32_t b1) {
    asm volatile(
        "mma.sync.aligned.m16n8k16.row.col.f32.bf16.bf16.f32 "
        "{%0,%1,%2,%3}, {%4,%5,%6,%7}, {%8,%9}, {%0,%1,%2,%3};"
        : "+f"(c0), "+f"(c1), "+f"(c2), "+f"(c3)
        : "r"(a0), "r"(a1), "r"(a2), "r"(a3), "r"(b0), "r"(b1));
}
__device__ __forceinline__ void split4(float4 v, uint2& hi, uint2& lo) {
    __nv_bfloat16 h0 = __float2bfloat16(v.x), h1 = __float2bfloat16(v.y);
    __nv_bfloat16 h2 = __float2bfloat16(v.z), h3 = __float2bfloat16(v.w);
    __nv_bfloat16 l0 = __float2bfloat16(v.x - __bfloat162float(h0));
    __nv_bfloat16 l1 = __float2bfloat16(v.y - __bfloat162float(h1));
    __nv_bfloat16 l2 = __float2bfloat16(v.z - __bfloat162float(h2));
    __nv_bfloat16 l3 = __float2bfloat16(v.w - __bfloat162float(h3));
    hi.x = (uint32_t)__bfloat16_as_ushort(h0) | ((uint32_t)__bfloat16_as_ushort(h1) << 16);
    hi.y = (uint32_t)__bfloat16_as_ushort(h2) | ((uint32_t)__bfloat16_as_ushort(h3) << 16);
    lo.x = (uint32_t)__bfloat16_as_ushort(l0) | ((uint32_t)__bfloat16_as_ushort(l1) << 16);
    lo.y = (uint32_t)__bfloat16_as_ushort(l2) | ((uint32_t)__bfloat16_as_ushort(l3) << 16);
}

// ---------------------------------------------------------------------------
// Kernel 0: split x into bf16 hi/lo
// ---------------------------------------------------------------------------
__global__ __launch_bounds__(256) void convert_x_kernel(const float* __restrict__ x)
{
    size_t i4 = (size_t)blockIdx.x * 256 + threadIdx.x;   // float4 index
    float4 v = __ldg((const float4*)x + i4);
    uint2 hi, lo;
    split4(v, hi, lo);
    *(uint2*)&g_Xh[i4 * 4] = hi;
    *(uint2*)&g_Xl[i4 * 4] = lo;
}

// ---------------------------------------------------------------------------
// Kernel 1: fold LoRA into W, output split bf16 hi/lo.
//   Weff[o,d] = W[o,d] + sum_k Bs[o,k] * A[k,d],  k = 16e + r, Bs masked
// ---------------------------------------------------------------------------
__global__ __launch_bounds__(256) void fold_kernel(
    const float* __restrict__ W,
    const float* __restrict__ A,          // lora_A as [128, D_IN]
    const float* __restrict__ Bl,         // [E, D_OUT, R]
    const int* __restrict__ mask)
{
    __shared__ __align__(16) float sB[16][132];
    __shared__ __align__(16) float sA[16][132];

    const int t  = threadIdx.x;
    const int tr = t >> 4;
    const int tc = t & 15;
    const int o0 = blockIdx.y * 128;
    const int d0 = blockIdx.x * 128;

    float acc[8][8];
#pragma unroll
    for (int i = 0; i < 8; ++i)
#pragma unroll
        for (int j = 0; j < 8; ++j) acc[i][j] = 0.f;

    for (int c = 0; c < NEXP; ++c) {
        const float sc = (mask[c] != 0) ? SCALING : 0.f;
#pragma unroll
        for (int i = 0; i < 8; ++i) {
            int idx = t + i * 256;
            int ol = idx >> 4, r = idx & 15;
            sB[r][ol] = Bl[(size_t)c * D_OUT * RANK + (size_t)(o0 + ol) * RANK + r] * sc;
        }
#pragma unroll
        for (int i = 0; i < 8; ++i) {
            int idx = t + i * 256;
            int kk = idx >> 7, dl = idx & 127;
            sA[kk][dl] = A[(size_t)(c * 16 + kk) * D_IN + d0 + dl];
        }
        __syncthreads();
#pragma unroll
        for (int kk = 0; kk < 16; ++kk) {
            float4 b0 = *(const float4*)&sB[kk][tr * 8];
            float4 b1 = *(const float4*)&sB[kk][tr * 8 + 4];
            float4 a0 = *(const float4*)&sA[kk][tc * 8];
            float4 a1 = *(const float4*)&sA[kk][tc * 8 + 4];
            float ov[8] = {b0.x, b0.y, b0.z, b0.w, b1.x, b1.y, b1.z, b1.w};
            float dv[8] = {a0.x, a0.y, a0.z, a0.w, a1.x, a1.y, a1.z, a1.w};
#pragma unroll
            for (int i = 0; i < 8; ++i)
#pragma unroll
                for (int j = 0; j < 8; ++j) acc[i][j] += ov[i] * dv[j];
        }
        __syncthreads();
    }

#pragma unroll
    for (int i = 0; i < 8; ++i) {
        int o = o0 + tr * 8 + i;
#pragma unroll
        for (int j = 0; j < 8; j += 4) {
            int d = d0 + tc * 8 + j;
            float4 w = *(const float4*)&W[(size_t)o * D_IN + d];
            float4 r;
            r.x = w.x + acc[i][j + 0]; r.y = w.y + acc[i][j + 1];
            r.z = w.z + acc[i][j + 2]; r.w = w.w + acc[i][j + 3];
            uint2 hi, lo;
            split4(r, hi, lo);
            *(uint2*)&g_Wh[(size_t)o * D_IN + d] = hi;
            *(uint2*)&g_Wl[(size_t)o * D_IN + d] = lo;
        }
    }
}

// ---------------------------------------------------------------------------
// Kernel 2: bf16x3 GEMM via mma.sync.m16n8k16.
//   out[m,n] = sum_k x[m,k]*Weff[n,k] + bias[n]
// BM=128 BN=128 BK=64, 256 threads = 8 warps (2m x 4n), warp tile 64x32.
// SMEM per stage: Xh,Xl,Wh,Wl tiles [128][64] bf16 (16KB each) = 64KB; 2 stages.
// Rows are 128B; store/load swizzle: seg' = seg ^ (row&7)  -> conflict-free.
// ---------------------------------------------------------------------------
#define BK 64
#define NKT (D_IN / BK)            // 32
#define TILE_B 16384               // bytes per tile
#define STG_B  (4 * TILE_B)        // 64KB per stage
#define SMEM_B (2 * STG_B)         // 128KB

__global__ __launch_bounds__(256, 1)
void gemm_mma_kernel(const float* __restrict__ bias, float* __restrict__ out)
{
    extern __shared__ __align__(1024) char smem[];
    const uint32_t sb = smem_u32(smem);

    const int t    = threadIdx.x;
    const int lane = t & 31;
    const int wid  = t >> 5;
    const int wm0  = (wid >> 2) * 64;     // warp m offset in tile
    const int wn0  = (wid & 3) * 32;      // warp n offset in tile
    const int n0   = blockIdx.x * 128;
    const int m0   = blockIdx.y * 128;

    // ldmatrix lane geometry (constant per thread)
    const int a_row = wm0 + (lane & 7) + ((lane >> 3) & 1) * 8;  // + mi*16
    const int a_ks  = (lane >> 4);                               // + 2*j
    const int b_row = wn0 + (lane & 7) + (lane >> 4) * 8;        // + ni2*16
    const int b_ks  = (lane >> 3) & 1;                           // + 2*j
    const int a_r7  = a_row & 7;
    const int b_r7  = b_row & 7;

    // cp.async chunk geometry: per tile 1024 x 16B chunks; 4 per thread per tile.
    // chunk c: row=c>>3, seg=c&7 ; smem off = row*128 + ((seg ^ (row&7))<<4)
    float acc[4][4][4];
#pragma unroll
    for (int i = 0; i < 4; ++i)
#pragma unroll
        for (int j = 0; j < 4; ++j)
#pragma unroll
            for (int q = 0; q < 4; ++q) acc[i][j][q] = 0.f;

    const __nv_bfloat16* gx[2] = { g_Xh, g_Xl };
    const __nv_bfloat16* gw[2] = { g_Wh, g_Wl };

    auto issue_stage = [&](int kt, int stg) {
        const uint32_t base = sb + stg * STG_B;
        const int kbase = kt * BK;
#pragma unroll
        for (int hl = 0; hl < 2; ++hl) {
#pragma unroll
            for (int ii = 0; ii < 4; ++ii) {
                int c = t + ii * 256;
                int row = c >> 3, seg = c & 7;
                uint32_t soff = (uint32_t)(row * 128 + ((seg ^ (row & 7)) << 4));
                // X tile (hl): tile index 0/1
                cpa16(base + hl * TILE_B + soff,
                      &gx[hl][(size_t)(m0 + row) * D_IN + kbase + seg * 8]);
                // W tile (hl): tile index 2/3
                cpa16(base + (2 + hl) * TILE_B + soff,
                      &gw[hl][(size_t)(n0 + row) * D_IN + kbase + seg * 8]);
            }
        }
        cpa_commit();
    };

    issue_stage(0, 0);

    for (int kt = 0; kt < NKT; ++kt) {
        const int stg = kt & 1;
        if (kt + 1 < NKT) issue_stage(kt + 1, stg ^ 1);
        if (kt + 1 < NKT) cpa_wait<1>(); else cpa_wait<0>();
        __syncthreads();

        const uint32_t xh = sb + stg * STG_B;
        const uint32_t xl = xh + TILE_B;
        const uint32_t wh = xh + 2 * TILE_B;
        const uint32_t wl = xh + 3 * TILE_B;

#pragma unroll
        for (int j = 0; j < 4; ++j) {               // k16 steps within BK=64
            uint32_t ah[4][4], al[4][4];
            const int aks = 2 * j + a_ks;
            const uint32_t axoff = (uint32_t)((aks ^ a_r7) << 4);
#pragma unroll
            for (int mi = 0; mi < 4; ++mi) {
                const uint32_t ro = (uint32_t)((a_row + mi * 16) * 128) + axoff;
                ldsm_x4(xh + ro, ah[mi][0], ah[mi][1], ah[mi][2], ah[mi][3]);
                ldsm_x4(xl + ro, al[mi][0], al[mi][1], al[mi][2], al[mi][3]);
            }
            uint32_t bh[2][4], bl[2][4];
            const int bks = 2 * j + b_ks;
            const uint32_t bxoff = (uint32_t)((bks ^ b_r7) << 4);
#pragma unroll
            for (int ni2 = 0; ni2 < 2; ++ni2) {
                const uint32_t ro = (uint32_t)((b_row + ni2 * 16) * 128) + bxoff;
                ldsm_x4(wh + ro, bh[ni2][0], bh[ni2][1], bh[ni2][2], bh[ni2][3]);
                ldsm_x4(wl + ro, bl[ni2][0], bl[ni2][1], bl[ni2][2], bl[ni2][3]);
            }
#pragma unroll
            for (int mi = 0; mi < 4; ++mi) {
#pragma unroll
                for (int ni = 0; ni < 4; ++ni) {
                    const int g = ni >> 1, o = (ni & 1) * 2;
                    float* c = acc[mi][ni];
                    mma_bf16(c[0], c[1], c[2], c[3],
                             ah[mi][0], ah[mi][1], ah[mi][2], ah[mi][3],
                             bh[g][o], bh[g][o + 1]);
                    mma_bf16(c[0], c[1], c[2], c[3],
                             ah[mi][0], ah[mi][1], ah[mi][2], ah[mi][3],
                             bl[g][o], bl[g][o + 1]);
                    mma_bf16(c[0], c[1], c[2], c[3],
                             al[mi][0], al[mi][1], al[mi][2], al[mi][3],
                             bh[g][o], bh[g][o + 1]);
                }
            }
        }
        __syncthreads();
    }

    // Epilogue: c layout m16n8: c0,c1 at (row=lane>>2, col=(lane&3)*2), c2,c3 at row+8.
    const int erow = lane >> 2;
    const int ecol = (lane & 3) * 2;
#pragma unroll
    for (int ni = 0; ni < 4; ++ni) {
        const int ncol = n0 + wn0 + ni * 8 + ecol;
        const float b0 = __ldg(&bias[ncol]);
        const float b1 = __ldg(&bias[ncol + 1]);
#pragma unroll
        for (int mi = 0; mi < 4; ++mi) {
            const int r0 = m0 + wm0 + mi * 16 + erow;
            float2 v0 = { acc[mi][ni][0] + b0, acc[mi][ni][1] + b1 };
            float2 v1 = { acc[mi][ni][2] + b0, acc[mi][ni][3] + b1 };
            *(float2*)&out[(size_t)r0 * D_OUT + ncol] = v0;
            *(float2*)&out[(size_t)(r0 + 8) * D_OUT + ncol] = v1;
        }
    }
}

// ---------------------------------------------------------------------------
// Inputs (metadata order): x, W, b, lora_A, lora_B, expert_mask
// ---------------------------------------------------------------------------
extern "C" void kernel_launch(void* const* d_in, const int* in_sizes, int n_in,
                              void* d_out, int out_size)
{
    const float* x    = (const float*)d_in[0];
    const float* W    = (const float*)d_in[1];
    const float* b    = (const float*)d_in[2];
    const float* lA   = (const float*)d_in[3];
    const float* lB   = (const float*)d_in[4];
    const int*   mask = (const int*)d_in[5];
    float* out = (float*)d_out;

    static bool attr_done = false;
    if (!attr_done) {
        cudaFuncSetAttribute(gemm_mma_kernel,
                             cudaFuncAttributeMaxDynamicSharedMemorySize, SMEM_B);
        attr_done = true;
    }

    dim3 blk(256);
    convert_x_kernel<<<(M_TOK * D_IN / 4) / 256, blk>>>(x);
    dim3 grid_fold(D_IN / 128, D_OUT / 128);
    fold_kernel<<<grid_fold, blk>>>(W, lA, lB, mask);
    dim3 grid_gemm(D_OUT / 128, M_TOK / 128);   // (16, 64)
    gemm_mma_kernel<<<grid_gemm, blk, SMEM_B>>>(b, out);
}

// round 5
// speedup vs baseline: 6.4471x; 2.2794x over previous
#include <cuda_runtime.h>
#include <cuda_fp16.h>
#include <cstdint>

#define D_IN   2048
#define D_OUT  2048
#define M_TOK  8192
#define RANK   16
#define NEXP   8
#define SCALING 1.0f

// fp16 operands, precomputed. 40MB total, static device globals.
__device__ __half g_Xh[(size_t)M_TOK * D_IN];
__device__ __half g_Wh[(size_t)D_OUT * D_IN];

// ---------------------------------------------------------------------------
// helpers
// ---------------------------------------------------------------------------
__device__ __forceinline__ uint32_t smem_u32(const void* p) {
    uint32_t a;
    asm("{ .reg .u64 t; cvta.to.shared.u64 t, %1; cvt.u32.u64 %0, t; }" : "=r"(a) : "l"(p));
    return a;
}
__device__ __forceinline__ void cpa16(uint32_t s, const void* g) {
    asm volatile("cp.async.cg.shared.global [%0], [%1], 16;" :: "r"(s), "l"(g));
}
__device__ __forceinline__ void cpa_commit() {
    asm volatile("cp.async.commit_group;" ::: "memory");
}
template <int N> __device__ __forceinline__ void cpa_wait() {
    asm volatile("cp.async.wait_group %0;" :: "n"(N) : "memory");
}
__device__ __forceinline__ void ldsm_x4(uint32_t addr, uint32_t& r0, uint32_t& r1,
                                        uint32_t& r2, uint32_t& r3) {
    asm volatile("ldmatrix.sync.aligned.m8n8.x4.shared.b16 {%0,%1,%2,%3}, [%4];"
                 : "=r"(r0), "=r"(r1), "=r"(r2), "=r"(r3) : "r"(addr));
}
__device__ __forceinline__ void mma_fp16(float& c0, float& c1, float& c2, float& c3,
                                         uint32_t a0, uint32_t a1, uint32_t a2, uint32_t a3,
                                         uint32_t b0, uint32_t b1) {
    asm volatile(
        "mma.sync.aligned.m16n8k16.row.col.f32.f16.f16.f32 "
        "{%0,%1,%2,%3}, {%4,%5,%6,%7}, {%8,%9}, {%0,%1,%2,%3};"
        : "+f"(c0), "+f"(c1), "+f"(c2), "+f"(c3)
        : "r"(a0), "r"(a1), "r"(a2), "r"(a3), "r"(b0), "r"(b1));
}
__device__ __forceinline__ uint2 pack_h4(float4 v) {
    __half2 p0 = __floats2half2_rn(v.x, v.y);
    __half2 p1 = __floats2half2_rn(v.z, v.w);
    uint2 u;
    u.x = *(uint32_t*)&p0;
    u.y = *(uint32_t*)&p1;
    return u;
}

// ---------------------------------------------------------------------------
// Kernel 0: convert x to fp16
// ---------------------------------------------------------------------------
__global__ __launch_bounds__(256) void convert_x_kernel(const float* __restrict__ x)
{
    size_t i4 = (size_t)blockIdx.x * 256 + threadIdx.x;   // float4 index
    float4 v = __ldg((const float4*)x + i4);
    *(uint2*)&g_Xh[i4 * 4] = pack_h4(v);
}

// ---------------------------------------------------------------------------
// Kernel 1: fold LoRA into W, output fp16.
//   Weff[o,d] = W[o,d] + sum_k Bs[o,k] * A[k,d],  k = 16e + r, Bs masked
// ---------------------------------------------------------------------------
__global__ __launch_bounds__(256) void fold_kernel(
    const float* __restrict__ W,
    const float* __restrict__ A,          // lora_A as [128, D_IN]
    const float* __restrict__ Bl,         // [E, D_OUT, R]
    const int* __restrict__ mask)
{
    __shared__ __align__(16) float sB[16][132];
    __shared__ __align__(16) float sA[16][132];

    const int t  = threadIdx.x;
    const int tr = t >> 4;
    const int tc = t & 15;
    const int o0 = blockIdx.y * 128;
    const int d0 = blockIdx.x * 128;

    float acc[8][8];
#pragma unroll
    for (int i = 0; i < 8; ++i)
#pragma unroll
        for (int j = 0; j < 8; ++j) acc[i][j] = 0.f;

    for (int c = 0; c < NEXP; ++c) {
        const float sc = (mask[c] != 0) ? SCALING : 0.f;
#pragma unroll
        for (int i = 0; i < 8; ++i) {
            int idx = t + i * 256;
            int ol = idx >> 4, r = idx & 15;
            sB[r][ol] = Bl[(size_t)c * D_OUT * RANK + (size_t)(o0 + ol) * RANK + r] * sc;
        }
#pragma unroll
        for (int i = 0; i < 8; ++i) {
            int idx = t + i * 256;
            int kk = idx >> 7, dl = idx & 127;
            sA[kk][dl] = A[(size_t)(c * 16 + kk) * D_IN + d0 + dl];
        }
        __syncthreads();
#pragma unroll
        for (int kk = 0; kk < 16; ++kk) {
            float4 b0 = *(const float4*)&sB[kk][tr * 8];
            float4 b1 = *(const float4*)&sB[kk][tr * 8 + 4];
            float4 a0 = *(const float4*)&sA[kk][tc * 8];
            float4 a1 = *(const float4*)&sA[kk][tc * 8 + 4];
            float ov[8] = {b0.x, b0.y, b0.z, b0.w, b1.x, b1.y, b1.z, b1.w};
            float dv[8] = {a0.x, a0.y, a0.z, a0.w, a1.x, a1.y, a1.z, a1.w};
#pragma unroll
            for (int i = 0; i < 8; ++i)
#pragma unroll
                for (int j = 0; j < 8; ++j) acc[i][j] += ov[i] * dv[j];
        }
        __syncthreads();
    }

#pragma unroll
    for (int i = 0; i < 8; ++i) {
        int o = o0 + tr * 8 + i;
#pragma unroll
        for (int j = 0; j < 8; j += 4) {
            int d = d0 + tc * 8 + j;
            float4 w = *(const float4*)&W[(size_t)o * D_IN + d];
            float4 r;
            r.x = w.x + acc[i][j + 0]; r.y = w.y + acc[i][j + 1];
            r.z = w.z + acc[i][j + 2]; r.w = w.w + acc[i][j + 3];
            *(uint2*)&g_Wh[(size_t)o * D_IN + d] = pack_h4(r);
        }
    }
}

// ---------------------------------------------------------------------------
// Kernel 2: fp16 GEMM via mma.sync.m16n8k16 (fp32 accumulate).
//   out[m,n] = sum_k x[m,k]*Weff[n,k] + bias[n]
// BM=128 BN=128 BK=64, 256 threads = 8 warps (2m x 4n), warp tile 64x32.
// SMEM per stage: X,W tiles [128][64] fp16 (16KB each) = 32KB; 2 stages = 64KB.
// Rows are 128B; store/load swizzle: seg' = seg ^ (row&7) -> conflict-free.
// ---------------------------------------------------------------------------
#define BK 64
#define NKT (D_IN / BK)            // 32
#define TILE_B 16384               // bytes per tile
#define STG_B  (2 * TILE_B)        // 32KB per stage
#define SMEM_B (2 * STG_B)         // 64KB

__global__ __launch_bounds__(256, 2)
void gemm_mma_kernel(const float* __restrict__ bias, float* __restrict__ out)
{
    extern __shared__ __align__(1024) char smem[];
    const uint32_t sb = smem_u32(smem);

    const int t    = threadIdx.x;
    const int lane = t & 31;
    const int wid  = t >> 5;
    const int wm0  = (wid >> 2) * 64;     // warp m offset in tile
    const int wn0  = (wid & 3) * 32;      // warp n offset in tile
    const int n0   = blockIdx.x * 128;
    const int m0   = blockIdx.y * 128;

    // ldmatrix lane geometry
    const int a_row = wm0 + (lane & 7) + ((lane >> 3) & 1) * 8;  // + mi*16
    const int a_ks  = (lane >> 4);                               // + 2*j
    const int b_row = wn0 + (lane & 7) + (lane >> 4) * 8;        // + ni2*16
    const int b_ks  = (lane >> 3) & 1;                           // + 2*j
    const int a_r7  = a_row & 7;
    const int b_r7  = b_row & 7;

    float acc[4][4][4];
#pragma unroll
    for (int i = 0; i < 4; ++i)
#pragma unroll
        for (int j = 0; j < 4; ++j)
#pragma unroll
            for (int q = 0; q < 4; ++q) acc[i][j][q] = 0.f;

    // cp.async: per stage 2 tiles x 1024 chunks of 16B; 8 chunks per thread.
    auto issue_stage = [&](int kt, int stg) {
        const uint32_t base = sb + stg * STG_B;
        const int kbase = kt * BK;
#pragma unroll
        for (int ii = 0; ii < 4; ++ii) {
            int c = t + ii * 256;
            int row = c >> 3, seg = c & 7;
            uint32_t soff = (uint32_t)(row * 128 + ((seg ^ (row & 7)) << 4));
            cpa16(base + soff,
                  &g_Xh[(size_t)(m0 + row) * D_IN + kbase + seg * 8]);
            cpa16(base + TILE_B + soff,
                  &g_Wh[(size_t)(n0 + row) * D_IN + kbase + seg * 8]);
        }
        cpa_commit();
    };

    issue_stage(0, 0);

    for (int kt = 0; kt < NKT; ++kt) {
        const int stg = kt & 1;
        if (kt + 1 < NKT) issue_stage(kt + 1, stg ^ 1);
        if (kt + 1 < NKT) cpa_wait<1>(); else cpa_wait<0>();
        __syncthreads();

        const uint32_t xh = sb + stg * STG_B;
        const uint32_t wh = xh + TILE_B;

#pragma unroll
        for (int j = 0; j < 4; ++j) {               // k16 steps within BK=64
            uint32_t ah[4][4];
            const int aks = 2 * j + a_ks;
            const uint32_t axoff = (uint32_t)((aks ^ a_r7) << 4);
#pragma unroll
            for (int mi = 0; mi < 4; ++mi) {
                const uint32_t ro = (uint32_t)((a_row + mi * 16) * 128) + axoff;
                ldsm_x4(xh + ro, ah[mi][0], ah[mi][1], ah[mi][2], ah[mi][3]);
            }
            uint32_t bh[2][4];
            const int bks = 2 * j + b_ks;
            const uint32_t bxoff = (uint32_t)((bks ^ b_r7) << 4);
#pragma unroll
            for (int ni2 = 0; ni2 < 2; ++ni2) {
                const uint32_t ro = (uint32_t)((b_row + ni2 * 16) * 128) + bxoff;
                ldsm_x4(wh + ro, bh[ni2][0], bh[ni2][1], bh[ni2][2], bh[ni2][3]);
            }
#pragma unroll
            for (int mi = 0; mi < 4; ++mi) {
#pragma unroll
                for (int ni = 0; ni < 4; ++ni) {
                    const int g = ni >> 1, o = (ni & 1) * 2;
                    float* c = acc[mi][ni];
                    mma_fp16(c[0], c[1], c[2], c[3],
                             ah[mi][0], ah[mi][1], ah[mi][2], ah[mi][3],
                             bh[g][o], bh[g][o + 1]);
                }
            }
        }
        __syncthreads();
    }

    // Epilogue: c layout m16n8: c0,c1 at (row=lane>>2, col=(lane&3)*2), c2,c3 at row+8.
    const int erow = lane >> 2;
    const int ecol = (lane & 3) * 2;
#pragma unroll
    for (int ni = 0; ni < 4; ++ni) {
        const int ncol = n0 + wn0 + ni * 8 + ecol;
        const float b0 = __ldg(&bias[ncol]);
        const float b1 = __ldg(&bias[ncol + 1]);
#pragma unroll
        for (int mi = 0; mi < 4; ++mi) {
            const int r0 = m0 + wm0 + mi * 16 + erow;
            float2 v0 = { acc[mi][ni][0] + b0, acc[mi][ni][1] + b1 };
            float2 v1 = { acc[mi][ni][2] + b0, acc[mi][ni][3] + b1 };
            *(float2*)&out[(size_t)r0 * D_OUT + ncol] = v0;
            *(float2*)&out[(size_t)(r0 + 8) * D_OUT + ncol] = v1;
        }
    }
}

// ---------------------------------------------------------------------------
// Inputs (metadata order): x, W, b, lora_A, lora_B, expert_mask
// ---------------------------------------------------------------------------
extern "C" void kernel_launch(void* const* d_in, const int* in_sizes, int n_in,
                              void* d_out, int out_size)
{
    const float* x    = (const float*)d_in[0];
    const float* W    = (const float*)d_in[1];
    const float* b    = (const float*)d_in[2];
    const float* lA   = (const float*)d_in[3];
    const float* lB   = (const float*)d_in[4];
    const int*   mask = (const int*)d_in[5];
    float* out = (float*)d_out;

    static bool attr_done = false;
    if (!attr_done) {
        cudaFuncSetAttribute(gemm_mma_kernel,
                             cudaFuncAttributeMaxDynamicSharedMemorySize, SMEM_B);
        attr_done = true;
    }

    dim3 blk(256);
    convert_x_kernel<<<(M_TOK * D_IN / 4) / 256, blk>>>(x);
    dim3 grid_fold(D_IN / 128, D_OUT / 128);
    fold_kernel<<<grid_fold, blk>>>(W, lA, lB, mask);
    dim3 grid_gemm(D_OUT / 128, M_TOK / 128);   // (16, 64)
    gemm_mma_kernel<<<grid_gemm, blk, SMEM_B>>>(b, out);
}